// round 2
// baseline (speedup 1.0000x reference)
#include <cuda_runtime.h>
#include <cuda_bf16.h>

// Problem constants (fixed shapes per reference)
#define NN    65536      // total nodes
#define BG    64         // graphs
#define NPG   1024       // nodes per graph
#define DD    512        // feature dim
#define DEG   32
#define EPG   (NPG*DEG)  // 32768 edges per graph
#define EE    (BG*EPG)   // 2097152 edges
#define DROPK 512        // nodes zeroed per graph

// Scratch (device globals — allocation is forbidden)
__device__ int   g_is64;
__device__ float g_h[NN];
__device__ float g_wb[NN];

// ---------------------------------------------------------------------------
// Kernel 0: detect whether src/dst arrived as int64 or int32 words.
// int32 buffer: word i in [32768, 65536) is a node id in [1024,2048) -> nonzero.
// int64 buffer (little-endian): every odd word is a high half of a small
// nonnegative value -> zero. Three odd indices decide deterministically.
// All indices < EE (the int32 word count), so always in-bounds.
// ---------------------------------------------------------------------------
__global__ void detect_kernel(const unsigned int* __restrict__ src_raw) {
    if (threadIdx.x == 0) {
        bool is64 = (src_raw[32769]  == 0u) &&
                    (src_raw[98305]  == 0u) &&
                    (src_raw[163841] == 0u);
        g_is64 = is64 ? 1 : 0;
    }
}

// ---------------------------------------------------------------------------
// Kernel 1: h[i] = dot(features[i], weight). One warp per row, float4 loads.
// Weight (512 floats) staged in shared once per block.
// ---------------------------------------------------------------------------
__global__ __launch_bounds__(256) void matvec_kernel(
    const float4* __restrict__ feat, const float4* __restrict__ w)
{
    __shared__ float4 w_s[DD / 4];
    if (threadIdx.x < DD / 4)
        w_s[threadIdx.x] = w[threadIdx.x];
    __syncthreads();

    int warp = (blockIdx.x * blockDim.x + threadIdx.x) >> 5;
    int lane = threadIdx.x & 31;
    if (warp >= NN) return;
    const float4* row = feat + (size_t)warp * (DD / 4);
    float sum = 0.f;
#pragma unroll
    for (int i = 0; i < 4; i++) {
        float4 f  = row[lane + i * 32];
        float4 ww = w_s[lane + i * 32];
        sum += f.x * ww.x + f.y * ww.y + f.z * ww.z + f.w * ww.w;
    }
#pragma unroll
    for (int o = 16; o; o >>= 1) sum += __shfl_down_sync(0xFFFFFFFFu, sum, o);
    if (lane == 0) g_h[warp] = sum;
}

// ---------------------------------------------------------------------------
// Kernel 2: per-graph. deg -> norm -> scatter agg (shared atomics) -> relu ->
// bitonic sort (threshold = DROPK-th smallest) -> masked scores wb.
// One 1024-thread CTA per graph; edges of graph g are contiguous
// [g*EPG, (g+1)*EPG) and node ids lie in [g*NPG, (g+1)*NPG), so local id is
// the low 10 bits.
// ---------------------------------------------------------------------------
__global__ __launch_bounds__(1024) void graph_kernel(
    const void* __restrict__ src_p, const void* __restrict__ dst_p,
    const float* __restrict__ bias)
{
    const int g   = blockIdx.x;
    const int tid = threadIdx.x;

    __shared__ float h_s[NPG];      // h, later reused to hold w
    __shared__ float hn_s[NPG];     // h * norm (source side)
    __shared__ float norm_s[NPG];
    __shared__ int   deg_s[NPG];
    __shared__ float agg_s[NPG];
    __shared__ float sort_s[NPG];
    __shared__ int   c_sh;
    __shared__ int   is64_sh;

    if (tid == 0) is64_sh = g_is64;
    h_s[tid]   = g_h[g * NPG + tid];
    deg_s[tid] = 0;
    agg_s[tid] = 0.f;
    __syncthreads();
    const bool is64  = (is64_sh != 0);
    const long ebase = (long)g * EPG;

    // Pass 1: in-degree
    #pragma unroll
    for (int r = 0; r < DEG; r++) {
        int e = r * NPG + tid;
        int d = is64 ? ((const int2*)dst_p)[ebase + e].x
                     : ((const int*)dst_p)[ebase + e];
        atomicAdd(&deg_s[d & (NPG - 1)], 1);
    }
    __syncthreads();

    {
        int   dg = deg_s[tid];
        float nm = (dg > 0) ? (1.0f / sqrtf((float)dg)) : 0.f;
        norm_s[tid] = nm;
        hn_s[tid]   = h_s[tid] * nm;
    }
    __syncthreads();

    // Pass 2: agg[dst] += (h*norm)[src]
    #pragma unroll
    for (int r = 0; r < DEG; r++) {
        int e = r * NPG + tid;
        int s, d;
        if (is64) {
            s = ((const int2*)src_p)[ebase + e].x;
            d = ((const int2*)dst_p)[ebase + e].x;
        } else {
            s = ((const int*)src_p)[ebase + e];
            d = ((const int*)dst_p)[ebase + e];
        }
        atomicAdd(&agg_s[d & (NPG - 1)], hn_s[s & (NPG - 1)]);
    }
    __syncthreads();

    float w = fmaxf(agg_s[tid] * norm_s[tid] + bias[0], 0.f);
    h_s[tid]    = w;       // keep per-node w
    sort_s[tid] = w;       // sorting copy
    __syncthreads();

    // Bitonic sort ascending (1024 elements, 1024 threads)
    for (int k = 2; k <= NPG; k <<= 1) {
        for (int j = k >> 1; j > 0; j >>= 1) {
            int ixj = tid ^ j;
            if (ixj > tid) {
                float a = sort_s[tid], b = sort_s[ixj];
                bool up = ((tid & k) == 0);
                if ((a > b) == up) { sort_s[tid] = b; sort_s[ixj] = a; }
            }
            __syncthreads();
        }
    }

    float T = sort_s[DROPK - 1];     // largest dropped value
    // first sorted index holding T (exactly one thread writes)
    if (sort_s[tid] == T && (tid == 0 || sort_s[tid - 1] < T)) c_sh = tid;
    __syncthreads();

    float wb;
    if (T == 0.f) {
        // Dropped zeros and kept zeros gate features identically (x*0 == x*0).
        wb = w;
    } else if (w < T) {
        wb = 0.f;
    } else if (w > T) {
        wb = w;
    } else {
        // Exact tie at T>0: stable rank — drop the first (DROPK - c_sh) ties
        // in node-index order (matches argsort(argsort) stability).
        int ndrop_ties = DROPK - c_sh;
        int t = 0;
        for (int j = 0; j < tid; j++) t += (h_s[j] == T);
        wb = (t < ndrop_ties) ? 0.f : w;
    }
    g_wb[g * NPG + tid] = wb;
}

// ---------------------------------------------------------------------------
// Kernel 3: out = features * wb[node]   (float4-vectorized stream)
// ---------------------------------------------------------------------------
__global__ __launch_bounds__(256) void gate_kernel(
    const float4* __restrict__ feat, float4* __restrict__ out)
{
    int idx = blockIdx.x * blockDim.x + threadIdx.x;   // over NN*DD/4 exactly
    int   node = idx >> 7;                              // DD/4 = 128
    float wv   = __ldg(&g_wb[node]);
    float4 f   = feat[idx];
    out[idx]   = make_float4(f.x * wv, f.y * wv, f.z * wv, f.w * wv);
}

// ---------------------------------------------------------------------------
extern "C" void kernel_launch(void* const* d_in, const int* in_sizes, int n_in,
                              void* d_out, int out_size) {
    const float* features = (const float*)d_in[0];
    const void*  src      = d_in[1];
    const void*  dst      = d_in[2];
    const float* weight   = (const float*)d_in[3];
    const float* bias     = (const float*)d_in[4];
    float*       out      = (float*)d_out;

    detect_kernel<<<1, 32>>>((const unsigned int*)src);

    matvec_kernel<<<NN / 8, 256>>>((const float4*)features, (const float4*)weight);

    graph_kernel<<<BG, 1024>>>(src, dst, bias);

    gate_kernel<<<(NN * (DD / 4)) / 256, 256>>>((const float4*)features, (float4*)out);
}

// round 3
// speedup vs baseline: 1.0850x; 1.0850x over previous
#include <cuda_runtime.h>
#include <cuda_bf16.h>

// Problem constants (fixed shapes per reference)
#define NN    65536      // total nodes
#define BG    64         // graphs
#define NPG   1024       // nodes per graph
#define DD    512        // feature dim
#define DEG   32
#define EPG   (NPG*DEG)  // 32768 edges per graph
#define EE    (BG*EPG)   // 2097152 edges
#define DROPK 512        // nodes zeroed per graph

// Scratch (device globals — allocation is forbidden)
__device__ int   g_is64;
__device__ float g_h[NN];
__device__ float g_wb[NN];

// ---------------------------------------------------------------------------
// Kernel 0: detect int64 vs int32 edge encoding (3 odd-word probes).
// ---------------------------------------------------------------------------
__global__ void detect_kernel(const unsigned int* __restrict__ src_raw) {
    if (threadIdx.x == 0) {
        bool is64 = (src_raw[32769]  == 0u) &&
                    (src_raw[98305]  == 0u) &&
                    (src_raw[163841] == 0u);
        g_is64 = is64 ? 1 : 0;
    }
}

// ---------------------------------------------------------------------------
// Kernel 1: h[i] = dot(features[i], weight). One warp per row, float4 loads.
// ---------------------------------------------------------------------------
__global__ __launch_bounds__(256) void matvec_kernel(
    const float4* __restrict__ feat, const float4* __restrict__ w)
{
    __shared__ float4 w_s[DD / 4];
    if (threadIdx.x < DD / 4)
        w_s[threadIdx.x] = w[threadIdx.x];
    __syncthreads();

    int warp = (blockIdx.x * blockDim.x + threadIdx.x) >> 5;
    int lane = threadIdx.x & 31;
    const float4* row = feat + (size_t)warp * (DD / 4);
    float sum = 0.f;
#pragma unroll
    for (int i = 0; i < 4; i++) {
        float4 f  = row[lane + i * 32];
        float4 ww = w_s[lane + i * 32];
        sum += f.x * ww.x + f.y * ww.y + f.z * ww.z + f.w * ww.w;
    }
#pragma unroll
    for (int o = 16; o; o >>= 1) sum += __shfl_down_sync(0xFFFFFFFFu, sum, o);
    if (lane == 0) g_h[warp] = sum;
}

// ---------------------------------------------------------------------------
// Kernel 2: per-graph. One 1024-thread CTA per graph.
// dst read ONCE from global (cached as u16 local ids in dynamic smem),
// deg -> norm -> scatter agg (shared atomics) -> relu -> bitonic threshold
// -> masked scores wb.
// Dynamic smem layout:
//   [0, 64K)        u16 dstc[EPG]
//   then floats:    h_s, hn_s, norm_s, agg_s, sort_s  (5 * 4KB)
//   then int:       deg_s (4KB)
// ---------------------------------------------------------------------------
#define GK_SMEM (EPG*2 + NPG*4*6)

extern __shared__ unsigned char gk_smem[];

__global__ __launch_bounds__(1024) void graph_kernel(
    const void* __restrict__ src_p, const void* __restrict__ dst_p,
    const float* __restrict__ bias)
{
    const int g   = blockIdx.x;
    const int tid = threadIdx.x;

    unsigned short* dstc   = (unsigned short*)gk_smem;
    float*          h_s    = (float*)(gk_smem + EPG*2);
    float*          hn_s   = h_s    + NPG;
    float*          norm_s = hn_s   + NPG;
    float*          agg_s  = norm_s + NPG;
    float*          sort_s = agg_s  + NPG;
    int*            deg_s  = (int*)(sort_s + NPG);

    __shared__ int c_sh;
    __shared__ int is64_sh;

    if (tid == 0) is64_sh = g_is64;
    h_s[tid]   = g_h[g * NPG + tid];
    deg_s[tid] = 0;
    agg_s[tid] = 0.f;
    __syncthreads();
    const bool is64  = (is64_sh != 0);
    const long ebase = (long)g * EPG;

    // Pass 1: in-degree + cache dst local ids in smem (single global read of dst)
    #pragma unroll
    for (int r = 0; r < DEG; r++) {
        int e = r * NPG + tid;
        int d = is64 ? ((const int2*)dst_p)[ebase + e].x
                     : ((const int*)dst_p)[ebase + e];
        d &= (NPG - 1);
        dstc[e] = (unsigned short)d;
        atomicAdd(&deg_s[d], 1);
    }
    __syncthreads();

    {
        int   dg = deg_s[tid];
        float nm = (dg > 0) ? (1.0f / sqrtf((float)dg)) : 0.f;
        norm_s[tid] = nm;
        hn_s[tid]   = h_s[tid] * nm;
    }
    __syncthreads();

    // Pass 2: agg[dst] += (h*norm)[src]   (src from global, dst from smem)
    #pragma unroll
    for (int r = 0; r < DEG; r++) {
        int e = r * NPG + tid;
        int s = is64 ? ((const int2*)src_p)[ebase + e].x
                     : ((const int*)src_p)[ebase + e];
        atomicAdd(&agg_s[dstc[e]], hn_s[s & (NPG - 1)]);
    }
    __syncthreads();

    float w = fmaxf(agg_s[tid] * norm_s[tid] + bias[0], 0.f);
    h_s[tid]    = w;       // keep per-node w
    sort_s[tid] = w;       // sorting copy
    __syncthreads();

    // Bitonic sort ascending (1024 elements, 1024 threads)
    for (int k = 2; k <= NPG; k <<= 1) {
        for (int j = k >> 1; j > 0; j >>= 1) {
            int ixj = tid ^ j;
            if (ixj > tid) {
                float a = sort_s[tid], b = sort_s[ixj];
                bool up = ((tid & k) == 0);
                if ((a > b) == up) { sort_s[tid] = b; sort_s[ixj] = a; }
            }
            __syncthreads();
        }
    }

    float T = sort_s[DROPK - 1];     // largest dropped value
    if (sort_s[tid] == T && (tid == 0 || sort_s[tid - 1] < T)) c_sh = tid;
    __syncthreads();

    float wb;
    if (T == 0.f) {
        // Dropped zeros and kept zeros gate features identically.
        wb = w;
    } else if (w < T) {
        wb = 0.f;
    } else if (w > T) {
        wb = w;
    } else {
        // Exact tie at T>0: stable rank — drop first (DROPK - c_sh) ties by index.
        int ndrop_ties = DROPK - c_sh;
        int t = 0;
        for (int j = 0; j < tid; j++) t += (h_s[j] == T);
        wb = (t < ndrop_ties) ? 0.f : w;
    }
    g_wb[g * NPG + tid] = wb;
}

// ---------------------------------------------------------------------------
// Kernel 3: out = features * wb[node], skipping the feature READ when wb==0.
// 2 float4 per thread (consecutive) -> 64 threads/node; branch is warp-uniform
// (node spans 4 warps at float4 granularity, 2 warps at float4x2).
// ---------------------------------------------------------------------------
__global__ __launch_bounds__(256) void gate_kernel(
    const float4* __restrict__ feat, float4* __restrict__ out)
{
    int t    = blockIdx.x * blockDim.x + threadIdx.x;   // over NN*DD/8
    int idx  = t * 2;                                    // float4 index
    int node = idx >> 7;                                 // 128 float4 per node
    float wv = __ldg(&g_wb[node]);
    if (wv != 0.f) {
        float4 f0 = feat[idx];
        float4 f1 = feat[idx + 1];
        out[idx]     = make_float4(f0.x * wv, f0.y * wv, f0.z * wv, f0.w * wv);
        out[idx + 1] = make_float4(f1.x * wv, f1.y * wv, f1.z * wv, f1.w * wv);
    } else {
        float4 z = make_float4(0.f, 0.f, 0.f, 0.f);
        out[idx]     = z;
        out[idx + 1] = z;
    }
}

// ---------------------------------------------------------------------------
extern "C" void kernel_launch(void* const* d_in, const int* in_sizes, int n_in,
                              void* d_out, int out_size) {
    const float* features = (const float*)d_in[0];
    const void*  src      = d_in[1];
    const void*  dst      = d_in[2];
    const float* weight   = (const float*)d_in[3];
    const float* bias     = (const float*)d_in[4];
    float*       out      = (float*)d_out;

    static int attr_done = 0;
    if (!attr_done) {
        cudaFuncSetAttribute(graph_kernel,
                             cudaFuncAttributeMaxDynamicSharedMemorySize, GK_SMEM);
        attr_done = 1;
    }

    detect_kernel<<<1, 32>>>((const unsigned int*)src);

    matvec_kernel<<<NN / 8, 256>>>((const float4*)features, (const float4*)weight);

    graph_kernel<<<BG, 1024, GK_SMEM>>>(src, dst, bias);

    gate_kernel<<<(NN * (DD / 8)) / 256, 256>>>((const float4*)features, (float4*)out);
}

// round 4
// speedup vs baseline: 1.1799x; 1.0874x over previous
#include <cuda_runtime.h>
#include <cuda_bf16.h>

#define NN    65536
#define BG    64
#define NPG   1024
#define DD    512
#define DEG   32
#define EPG   (NPG*DEG)
#define EE    (BG*EPG)
#define DROPK 512
#define SPLIT 8                 // CTAs per graph for edge kernels
#define ECTA  (EPG/SPLIT)       // 4096 edges per CTA

// Device scratch (no allocation allowed)
__device__ int   g_is64;
__device__ int   g_deg[NN];
__device__ float g_hn[NN];      // h * norm
__device__ float g_norm[NN];
__device__ float g_agg[NN];
__device__ float g_wb[NN];

// ---------------------------------------------------------------------------
// Kernel 0: zero g_deg/g_agg + detect int64 vs int32 edge words.
// grid 64 x 1024 -> 65536 threads, one element of each array per thread.
// ---------------------------------------------------------------------------
__global__ __launch_bounds__(1024) void zero_detect_kernel(
    const unsigned int* __restrict__ src_raw)
{
    int i = blockIdx.x * 1024 + threadIdx.x;
    g_deg[i] = 0;
    g_agg[i] = 0.f;
    if (i == 0) {
        bool is64 = (src_raw[32769]  == 0u) &&
                    (src_raw[98305]  == 0u) &&
                    (src_raw[163841] == 0u);
        g_is64 = is64 ? 1 : 0;
    }
}

// ---------------------------------------------------------------------------
// Kernel 1: in-degree. 512 CTAs (8 per graph), shared partial histogram,
// spread-address global atomic combine.
// ---------------------------------------------------------------------------
__global__ __launch_bounds__(1024) void deg_kernel(const void* __restrict__ dst_p)
{
    __shared__ int deg_s[NPG];
    const int tid = threadIdx.x;
    const int g   = blockIdx.x >> 3;             // SPLIT = 8
    deg_s[tid] = 0;
    __syncthreads();
    const bool is64  = (g_is64 != 0);
    const long ebase = (long)blockIdx.x * ECTA;
    #pragma unroll
    for (int r = 0; r < ECTA / NPG; r++) {       // 4 iters
        long e = ebase + r * NPG + tid;
        int d = is64 ? ((const int2*)dst_p)[e].x
                     : ((const int*)dst_p)[e];
        atomicAdd(&deg_s[d & (NPG - 1)], 1);
    }
    __syncthreads();
    int c = deg_s[tid];
    if (c) atomicAdd(&g_deg[g * NPG + tid], c);
}

// ---------------------------------------------------------------------------
// Kernel 2: matvec + norm epilogue. One warp per row; writes hn = h*norm
// and norm (runs after deg_kernel).
// ---------------------------------------------------------------------------
__global__ __launch_bounds__(256) void matvec_kernel(
    const float4* __restrict__ feat, const float4* __restrict__ w)
{
    __shared__ float4 w_s[DD / 4];
    if (threadIdx.x < DD / 4)
        w_s[threadIdx.x] = w[threadIdx.x];
    __syncthreads();

    int warp = (blockIdx.x * blockDim.x + threadIdx.x) >> 5;
    int lane = threadIdx.x & 31;
    const float4* row = feat + (size_t)warp * (DD / 4);
    float sum = 0.f;
#pragma unroll
    for (int i = 0; i < 4; i++) {
        float4 f  = row[lane + i * 32];
        float4 ww = w_s[lane + i * 32];
        sum += f.x * ww.x + f.y * ww.y + f.z * ww.z + f.w * ww.w;
    }
#pragma unroll
    for (int o = 16; o; o >>= 1) sum += __shfl_down_sync(0xFFFFFFFFu, sum, o);
    if (lane == 0) {
        int   dg = g_deg[warp];
        float nm = (dg > 0) ? rsqrtf((float)dg) : 0.f;
        g_norm[warp] = nm;
        g_hn[warp]   = sum * nm;
    }
}

// ---------------------------------------------------------------------------
// Kernel 3: scatter agg[dst] += hn[src]. 512 CTAs, shared partials,
// global atomic combine. hn working set per graph is 4 KB -> L1-resident.
// ---------------------------------------------------------------------------
__global__ __launch_bounds__(1024) void scatter_kernel(
    const void* __restrict__ src_p, const void* __restrict__ dst_p)
{
    __shared__ float agg_s[NPG];
    const int tid = threadIdx.x;
    const int g   = blockIdx.x >> 3;
    agg_s[tid] = 0.f;
    __syncthreads();
    const bool is64  = (g_is64 != 0);
    const long ebase = (long)blockIdx.x * ECTA;
    #pragma unroll
    for (int r = 0; r < ECTA / NPG; r++) {
        long e = ebase + r * NPG + tid;
        int s, d;
        if (is64) {
            s = ((const int2*)src_p)[e].x;
            d = ((const int2*)dst_p)[e].x;
        } else {
            s = ((const int*)src_p)[e];
            d = ((const int*)dst_p)[e];
        }
        atomicAdd(&agg_s[d & (NPG - 1)], g_hn[s]);
    }
    __syncthreads();
    float a = agg_s[tid];
    if (a != 0.f) atomicAdd(&g_agg[g * NPG + tid], a);
}

// ---------------------------------------------------------------------------
// Kernel 4: finalize per graph: w = relu(agg*norm + bias), hybrid bitonic
// (shfl for j<=16, shared for j>=32), threshold mask -> wb. 64 CTAs x 1024.
// ---------------------------------------------------------------------------
__global__ __launch_bounds__(1024) void finalize_kernel(const float* __restrict__ bias)
{
    __shared__ float sort_s[NPG];
    __shared__ float w_s[NPG];
    __shared__ int   c_sh;

    const int g   = blockIdx.x;
    const int tid = threadIdx.x;
    const int i   = g * NPG + tid;

    float w = fmaxf(g_agg[i] * g_norm[i] + bias[0], 0.f);
    w_s[tid] = w;
    float v  = w;

    // Bitonic sort ascending over tid; shared only for cross-warp stages.
    for (int k = 2; k <= NPG; k <<= 1) {
        bool dir_up = ((tid & k) == 0);
        for (int j = k >> 1; j >= 32; j >>= 1) {
            sort_s[tid] = v;
            __syncthreads();
            float other = sort_s[tid ^ j];
            __syncthreads();
            bool lower = ((tid & j) == 0);
            float mn = fminf(v, other), mx = fmaxf(v, other);
            v = (lower == dir_up) ? mn : mx;
        }
        int j0 = (k >> 1 < 32) ? (k >> 1) : 16;
        for (int j = j0; j > 0; j >>= 1) {
            float other = __shfl_xor_sync(0xFFFFFFFFu, v, j);
            bool lower = ((tid & j) == 0);
            float mn = fminf(v, other), mx = fmaxf(v, other);
            v = (lower == dir_up) ? mn : mx;
        }
    }
    sort_s[tid] = v;
    __syncthreads();

    float T = sort_s[DROPK - 1];                 // largest dropped value
    if (sort_s[tid] == T && (tid == 0 || sort_s[tid - 1] < T)) c_sh = tid;
    __syncthreads();

    float wb;
    if (T == 0.f) {
        wb = w;                                  // zero-gating identical either way
    } else if (w < T) {
        wb = 0.f;
    } else if (w > T) {
        wb = w;
    } else {
        // Exact tie at T>0: stable rank — drop first (DROPK - c_sh) ties by index.
        int ndrop_ties = DROPK - c_sh;
        int t = 0;
        for (int j = 0; j < tid; j++) t += (w_s[j] == T);
        wb = (t < ndrop_ties) ? 0.f : w;
    }
    g_wb[i] = wb;
}

// ---------------------------------------------------------------------------
// Kernel 5: gate. One warp per node, 4 float4 per lane; wv warp-uniform,
// skip the feature read when wv == 0.
// ---------------------------------------------------------------------------
__global__ __launch_bounds__(256) void gate_kernel(
    const float4* __restrict__ feat, float4* __restrict__ out)
{
    int gt   = blockIdx.x * blockDim.x + threadIdx.x;
    int node = gt >> 5;
    int lane = gt & 31;
    float wv = g_wb[node];
    size_t base = (size_t)node * (DD / 4) + lane;
    if (wv != 0.f) {
        float4 f0 = feat[base];
        float4 f1 = feat[base + 32];
        float4 f2 = feat[base + 64];
        float4 f3 = feat[base + 96];
        out[base]      = make_float4(f0.x*wv, f0.y*wv, f0.z*wv, f0.w*wv);
        out[base + 32] = make_float4(f1.x*wv, f1.y*wv, f1.z*wv, f1.w*wv);
        out[base + 64] = make_float4(f2.x*wv, f2.y*wv, f2.z*wv, f2.w*wv);
        out[base + 96] = make_float4(f3.x*wv, f3.y*wv, f3.z*wv, f3.w*wv);
    } else {
        float4 z = make_float4(0.f, 0.f, 0.f, 0.f);
        out[base]      = z;
        out[base + 32] = z;
        out[base + 64] = z;
        out[base + 96] = z;
    }
}

// ---------------------------------------------------------------------------
extern "C" void kernel_launch(void* const* d_in, const int* in_sizes, int n_in,
                              void* d_out, int out_size) {
    const float* features = (const float*)d_in[0];
    const void*  src      = d_in[1];
    const void*  dst      = d_in[2];
    const float* weight   = (const float*)d_in[3];
    const float* bias     = (const float*)d_in[4];
    float*       out      = (float*)d_out;

    zero_detect_kernel<<<BG, 1024>>>((const unsigned int*)src);
    deg_kernel<<<BG * SPLIT, 1024>>>(dst);
    matvec_kernel<<<NN / 8, 256>>>((const float4*)features, (const float4*)weight);
    scatter_kernel<<<BG * SPLIT, 1024>>>(src, dst);
    finalize_kernel<<<BG, 1024>>>(bias);
    gate_kernel<<<(NN * 32) / 256, 256>>>((const float4*)features, (float4*)out);
}

// round 5
// speedup vs baseline: 1.2674x; 1.0741x over previous
#include <cuda_runtime.h>
#include <cuda_bf16.h>

#define NN    65536
#define BG    64
#define NPG   1024
#define DD    512
#define DEG   32
#define EPG   (NPG*DEG)
#define EE    (BG*EPG)
#define DROPK 512
#define SPLIT 8                  // split-CTAs per graph for edge passes
#define NSPLITB (BG*SPLIT)       // 512
#define ECTA  (EPG/SPLIT)        // 4096 edges per split block

// Device scratch (no allocation allowed)
__device__ float g_h[NN];
__device__ int   g_deg_part[NSPLITB * NPG];   // 2 MB, non-atomic partials
__device__ float g_agg_part[NSPLITB * NPG];   // 2 MB, non-atomic partials
__device__ float g_wb[NN];

// int64 vs int32 edge-word probe: for int32, word i in [32768,65536) is a node
// id in [1024,2048) -> nonzero; for little-endian int64, odd words are zero
// high halves. 3 probes decide. All probed words L2-hit after first block.
__device__ __forceinline__ bool edges_are_i64(const unsigned int* p) {
    return (p[32769] == 0u) && (p[98305] == 0u) && (p[163841] == 0u);
}

// ---------------------------------------------------------------------------
// K1: fused. Blocks [0,512): per-split in-degree histograms (shared atomics,
// non-atomic partial writeback). Blocks [512, 512+8192): matvec h = feat @ w,
// one warp per row. The deg work (ATOMS pipe) hides under the matvec DRAM
// stream.
// ---------------------------------------------------------------------------
__global__ __launch_bounds__(256) void k1_deg_matvec(
    const float4* __restrict__ feat, const float4* __restrict__ w,
    const void* __restrict__ dst_p, const unsigned int* __restrict__ src_raw)
{
    __shared__ __align__(16) unsigned char sm_raw[NPG * 4];   // 4 KB

    if (blockIdx.x < NSPLITB) {
        // ---- degree partial for split block b ----
        int* deg_s = (int*)sm_raw;
        const int tid = threadIdx.x;
        const bool is64 = edges_are_i64(src_raw);   // src/dst share dtype
        #pragma unroll
        for (int r = 0; r < 4; r++) deg_s[r * 256 + tid] = 0;
        __syncthreads();
        const long ebase = (long)blockIdx.x * ECTA;
        #pragma unroll
        for (int r = 0; r < ECTA / 256; r++) {      // 16 iters
            long e = ebase + r * 256 + tid;
            int d = is64 ? ((const int2*)dst_p)[e].x
                         : ((const int*)dst_p)[e];
            atomicAdd(&deg_s[d & (NPG - 1)], 1);
        }
        __syncthreads();
        int* part = g_deg_part + (size_t)blockIdx.x * NPG;
        #pragma unroll
        for (int r = 0; r < 4; r++) {
            int i = r * 256 + tid;
            part[i] = deg_s[i];
        }
    } else {
        // ---- matvec: 8 warps -> 8 rows per block ----
        float4* w_s = (float4*)sm_raw;              // 128 float4 = 2 KB
        if (threadIdx.x < DD / 4)
            w_s[threadIdx.x] = w[threadIdx.x];
        __syncthreads();

        int warp = ((blockIdx.x - NSPLITB) * 256 + threadIdx.x) >> 5;
        int lane = threadIdx.x & 31;
        const float4* row = feat + (size_t)warp * (DD / 4);
        float sum = 0.f;
        #pragma unroll
        for (int i = 0; i < 4; i++) {
            float4 f  = row[lane + i * 32];
            float4 ww = w_s[lane + i * 32];
            sum += f.x * ww.x + f.y * ww.y + f.z * ww.z + f.w * ww.w;
        }
        #pragma unroll
        for (int o = 16; o; o >>= 1) sum += __shfl_down_sync(0xFFFFFFFFu, sum, o);
        if (lane == 0) g_h[warp] = sum;
    }
}

// ---------------------------------------------------------------------------
// K2: scatter. 512 blocks x 1024 threads (8 per graph, 4096 edges each).
// Reconstruct hn = h * deg^-1/2 for the whole graph into shared, then
// agg_s[dst] += hn_s[src] with shared atomics; write non-atomic partial.
// ---------------------------------------------------------------------------
__global__ __launch_bounds__(1024) void k2_scatter(
    const void* __restrict__ src_p, const void* __restrict__ dst_p,
    const unsigned int* __restrict__ src_raw)
{
    __shared__ float hn_s[NPG];
    __shared__ float agg_s[NPG];
    const int tid = threadIdx.x;
    const int g   = blockIdx.x >> 3;            // SPLIT = 8
    const bool is64 = edges_are_i64(src_raw);

    // hn for this graph's nodes (redundant across the 8 split blocks; cheap)
    {
        int dg = 0;
        #pragma unroll
        for (int s = 0; s < SPLIT; s++)
            dg += g_deg_part[(size_t)(g * SPLIT + s) * NPG + tid];
        float h = g_h[g * NPG + tid];
        hn_s[tid]  = (dg > 0) ? h * rsqrtf((float)dg) : 0.f;
        agg_s[tid] = 0.f;
    }
    __syncthreads();

    const long ebase = (long)blockIdx.x * ECTA;
    #pragma unroll
    for (int r = 0; r < ECTA / NPG; r++) {      // 4 iters
        long e = ebase + r * NPG + tid;
        int s, d;
        if (is64) {
            s = ((const int2*)src_p)[e].x;
            d = ((const int2*)dst_p)[e].x;
        } else {
            s = ((const int*)src_p)[e];
            d = ((const int*)dst_p)[e];
        }
        atomicAdd(&agg_s[d & (NPG - 1)], hn_s[s & (NPG - 1)]);
    }
    __syncthreads();
    g_agg_part[(size_t)blockIdx.x * NPG + tid] = agg_s[tid];
}

// ---------------------------------------------------------------------------
// K3: finalize per graph: sum partials, w = relu(agg*norm + bias), hybrid
// bitonic (shfl intra-warp, shared cross-warp), threshold mask -> wb.
// ---------------------------------------------------------------------------
__global__ __launch_bounds__(1024) void k3_finalize(const float* __restrict__ bias)
{
    __shared__ float sort_s[NPG];
    __shared__ float w_s[NPG];
    __shared__ int   c_sh;

    const int g   = blockIdx.x;
    const int tid = threadIdx.x;

    float agg = 0.f;
    int   dg  = 0;
    #pragma unroll
    for (int s = 0; s < SPLIT; s++) {
        size_t p = (size_t)(g * SPLIT + s) * NPG + tid;
        agg += g_agg_part[p];
        dg  += g_deg_part[p];
    }
    float nm = (dg > 0) ? rsqrtf((float)dg) : 0.f;
    float w  = fmaxf(agg * nm + bias[0], 0.f);
    w_s[tid] = w;
    float v  = w;

    // Bitonic sort ascending; shared only for cross-warp stages.
    for (int k = 2; k <= NPG; k <<= 1) {
        bool dir_up = ((tid & k) == 0);
        for (int j = k >> 1; j >= 32; j >>= 1) {
            sort_s[tid] = v;
            __syncthreads();
            float other = sort_s[tid ^ j];
            __syncthreads();
            bool lower = ((tid & j) == 0);
            float mn = fminf(v, other), mx = fmaxf(v, other);
            v = (lower == dir_up) ? mn : mx;
        }
        int j0 = (k >> 1 < 32) ? (k >> 1) : 16;
        for (int j = j0; j > 0; j >>= 1) {
            float other = __shfl_xor_sync(0xFFFFFFFFu, v, j);
            bool lower = ((tid & j) == 0);
            float mn = fminf(v, other), mx = fmaxf(v, other);
            v = (lower == dir_up) ? mn : mx;
        }
    }
    sort_s[tid] = v;
    __syncthreads();

    float T = sort_s[DROPK - 1];                 // largest dropped value
    if (sort_s[tid] == T && (tid == 0 || sort_s[tid - 1] < T)) c_sh = tid;
    __syncthreads();

    float wb;
    if (T == 0.f) {
        wb = w;                                  // zero gating identical either way
    } else if (w < T) {
        wb = 0.f;
    } else if (w > T) {
        wb = w;
    } else {
        // Exact tie at T>0: stable rank — drop first (DROPK - c_sh) ties by index.
        int ndrop_ties = DROPK - c_sh;
        int t = 0;
        for (int j = 0; j < tid; j++) t += (w_s[j] == T);
        wb = (t < ndrop_ties) ? 0.f : w;
    }
    g_wb[g * NPG + tid] = wb;
}

// ---------------------------------------------------------------------------
// K4: gate. One warp per node, 4 float4 per lane; wv warp-uniform, feature
// read skipped when wv == 0 (output is exactly zero there).
// ---------------------------------------------------------------------------
__global__ __launch_bounds__(256) void k4_gate(
    const float4* __restrict__ feat, float4* __restrict__ out)
{
    int gt   = blockIdx.x * blockDim.x + threadIdx.x;
    int node = gt >> 5;
    int lane = gt & 31;
    float wv = g_wb[node];
    size_t base = (size_t)node * (DD / 4) + lane;
    if (wv != 0.f) {
        float4 f0 = feat[base];
        float4 f1 = feat[base + 32];
        float4 f2 = feat[base + 64];
        float4 f3 = feat[base + 96];
        out[base]      = make_float4(f0.x*wv, f0.y*wv, f0.z*wv, f0.w*wv);
        out[base + 32] = make_float4(f1.x*wv, f1.y*wv, f1.z*wv, f1.w*wv);
        out[base + 64] = make_float4(f2.x*wv, f2.y*wv, f2.z*wv, f2.w*wv);
        out[base + 96] = make_float4(f3.x*wv, f3.y*wv, f3.z*wv, f3.w*wv);
    } else {
        float4 z = make_float4(0.f, 0.f, 0.f, 0.f);
        out[base]      = z;
        out[base + 32] = z;
        out[base + 64] = z;
        out[base + 96] = z;
    }
}

// ---------------------------------------------------------------------------
extern "C" void kernel_launch(void* const* d_in, const int* in_sizes, int n_in,
                              void* d_out, int out_size) {
    const float* features = (const float*)d_in[0];
    const void*  src      = d_in[1];
    const void*  dst      = d_in[2];
    const float* weight   = (const float*)d_in[3];
    const float* bias     = (const float*)d_in[4];
    float*       out      = (float*)d_out;

    k1_deg_matvec<<<NSPLITB + NN / 8, 256>>>(
        (const float4*)features, (const float4*)weight, dst,
        (const unsigned int*)src);

    k2_scatter<<<NSPLITB, 1024>>>(src, dst, (const unsigned int*)src);

    k3_finalize<<<BG, 1024>>>(bias);

    k4_gate<<<(NN * 32) / 256, 256>>>((const float4*)features, (float4*)out);
}